// round 2
// baseline (speedup 1.0000x reference)
#include <cuda_runtime.h>
#include <math.h>

#define BATCH 2
#define SEQ 2048
#define DMODEL 1024
#define NH 16
#define HD 64
#define DFF 4096
#define ROWS (BATCH*SEQ)   // 4096
#define STRD 68            // padded smem row stride (floats) for flash tiles

// -------- scratch (allocation-free rule: __device__ globals) --------
__device__ float g_q[BATCH*NH*SEQ*HD];
__device__ float g_k[BATCH*NH*SEQ*HD];
__device__ float g_v[BATCH*NH*SEQ*HD];
__device__ float g_attn[ROWS*DMODEL];
__device__ float g_x1[ROWS*DMODEL];
__device__ float g_src2[ROWS*DMODEL];
__device__ float g_ff[(size_t)ROWS*DFF];
__device__ int   g_len[BATCH];

// -------- sequence lengths from padding mask (dtype-robust) --------
// Mask semantics: True for padded (tail) positions, monotone per batch row.
// The harness may deliver the bool mask widened to int32 OR as raw bytes.
// Detection: view the first 1024 words. If the data is packed uint8, the
// tail-of-ones produces words like 0x01010101 (>1). If it is int32, the
// first 1024 elements belong to positions 0..1023 < len (len >= S/2), so
// every word is 0 or 1.
__global__ void len_k(const void* __restrict__ mask)
{
    const int b = blockIdx.x;
    __shared__ int sbyte;
    __shared__ int smin;
    if (threadIdx.x == 0) { sbyte = 0; smin = SEQ; }
    __syncthreads();

    const unsigned* w = (const unsigned*)mask;
    for (int i = threadIdx.x; i < 1024; i += blockDim.x) {
        if (w[i] > 1u) { sbyte = 1; break; }
    }
    __syncthreads();

    int local = SEQ;
    if (sbyte) {
        const unsigned char* m = (const unsigned char*)mask + (size_t)b * SEQ;
        for (int s = threadIdx.x; s < SEQ; s += blockDim.x)
            if (m[s]) { local = s; break; }   // monotone: first hit is thread-min
    } else {
        const int* m = (const int*)mask + (size_t)b * SEQ;
        for (int s = threadIdx.x; s < SEQ; s += blockDim.x)
            if (m[s]) { local = s; break; }
    }
    atomicMin(&smin, local);
    __syncthreads();
    if (threadIdx.x == 0) g_len[b] = smin;
}

// -------- SGEMM: C[M,N] = A[M,K] @ W[K,N] (+ epilogue) --------
// EPI 1: +bias, remap to [B,H,S,hd]
// EPI 2: +bias +res
// EPI 3: +bias, exact GELU
__device__ __forceinline__ float gelu_exact(float x) {
    return 0.5f * x * (1.0f + erff(x * 0.70710678118654752f));
}

template<int EPI>
__global__ __launch_bounds__(256, 1) void sgemm_k(
    const float* __restrict__ A, const float* __restrict__ W,
    const float* __restrict__ bias, const float* __restrict__ res,
    float* __restrict__ C, int M, int N, int K)
{
    __shared__ float As[8][128];
    __shared__ float Bs[8][128];
    const int tid = threadIdx.x;
    const int tx  = tid & 15;
    const int ty  = tid >> 4;
    const int row0 = blockIdx.y * 128;
    const int col0 = blockIdx.x * 128;

    const int a_row = tid >> 1;          // 0..127
    const int a_col = (tid & 1) * 4;     // 0 or 4
    const int b_row = tid >> 5;          // 0..7
    const int b_col = (tid & 31) * 4;    // 0..124

    const float* Ap = A + (size_t)(row0 + a_row) * K + a_col;
    const float* Bp = W + (size_t)b_row * N + col0 + b_col;

    float acc[8][8];
    #pragma unroll
    for (int i = 0; i < 8; i++)
        #pragma unroll
        for (int j = 0; j < 8; j++) acc[i][j] = 0.f;

    for (int k0 = 0; k0 < K; k0 += 8) {
        float4 av = *(const float4*)(Ap + k0);
        As[a_col+0][a_row] = av.x;
        As[a_col+1][a_row] = av.y;
        As[a_col+2][a_row] = av.z;
        As[a_col+3][a_row] = av.w;
        float4 bv = *(const float4*)(Bp + (size_t)k0 * N);
        *(float4*)&Bs[b_row][b_col] = bv;
        __syncthreads();
        #pragma unroll
        for (int kk = 0; kk < 8; kk++) {
            float ar[8], br[8];
            *(float4*)(ar)   = *(const float4*)&As[kk][ty*8];
            *(float4*)(ar+4) = *(const float4*)&As[kk][ty*8+4];
            *(float4*)(br)   = *(const float4*)&Bs[kk][tx*8];
            *(float4*)(br+4) = *(const float4*)&Bs[kk][tx*8+4];
            #pragma unroll
            for (int i = 0; i < 8; i++)
                #pragma unroll
                for (int j = 0; j < 8; j++)
                    acc[i][j] = fmaf(ar[i], br[j], acc[i][j]);
        }
        __syncthreads();
    }

    #pragma unroll
    for (int i = 0; i < 8; i++) {
        const int m = row0 + ty*8 + i;
        #pragma unroll
        for (int j = 0; j < 8; j += 4) {
            const int n = col0 + tx*8 + j;
            float4 o;
            o.x = acc[i][j]   + bias[n];
            o.y = acc[i][j+1] + bias[n+1];
            o.z = acc[i][j+2] + bias[n+2];
            o.w = acc[i][j+3] + bias[n+3];
            if (EPI == 1) {
                const int b = m >> 11, s = m & 2047;     // SEQ = 2048
                const int h = n >> 6,  d = n & 63;       // HD = 64
                *(float4*)&C[((size_t)((b*NH + h)*SEQ + s))*HD + d] = o;
            } else if (EPI == 2) {
                const float4 r = *(const float4*)&res[(size_t)m*N + n];
                o.x += r.x; o.y += r.y; o.z += r.z; o.w += r.w;
                *(float4*)&C[(size_t)m*N + n] = o;
            } else { // EPI == 3
                o.x = gelu_exact(o.x); o.y = gelu_exact(o.y);
                o.z = gelu_exact(o.z); o.w = gelu_exact(o.w);
                *(float4*)&C[(size_t)m*N + n] = o;
            }
        }
    }
}

// -------- flash attention: 64 q-rows per block, kv tiles of 64 --------
__global__ __launch_bounds__(256, 1) void flash_k(
    const float* __restrict__ Q, const float* __restrict__ K,
    const float* __restrict__ V, float* __restrict__ O)
{
    extern __shared__ float sm[];
    float* Qs = sm;                 // [64][STRD]
    float* Ks = sm + 64*STRD;       // [64][STRD], aliased as Ps after scores
    float* Vs = sm + 2*64*STRD;     // [64][STRD]

    const int qb = blockIdx.x, h = blockIdx.y, b = blockIdx.z;
    const int q0 = qb * 64;
    const int tid = threadIdx.x;
    const int tx = tid & 15, ty = tid >> 4;
    const int r0 = ty * 4, c0 = tx * 4;

    const size_t base = ((size_t)(b*NH + h)) * SEQ * HD;
    const float* Qp = Q + base + (size_t)q0 * HD;

    // load Q tile (pre-scaled by 1/sqrt(hd) = 0.125)
    for (int t = tid; t < 64*16; t += 256) {
        const int row = t >> 4, c4 = (t & 15) * 4;
        float4 v = *(const float4*)(Qp + row*HD + c4);
        v.x *= 0.125f; v.y *= 0.125f; v.z *= 0.125f; v.w *= 0.125f;
        *(float4*)&Qs[row*STRD + c4] = v;
    }

    const int len = g_len[b];
    float m[4], l[4], o[4][4];
    #pragma unroll
    for (int i = 0; i < 4; i++) {
        m[i] = -1e30f; l[i] = 0.f;
        #pragma unroll
        for (int j = 0; j < 4; j++) o[i][j] = 0.f;
    }

    const int kmax = min(q0 + 63, len - 1);
    for (int k0 = 0; k0 <= kmax; k0 += 64) {
        __syncthreads();   // Qs ready / previous tile's Ps,Vs reads done
        const float* Kp = K + base + (size_t)k0 * HD;
        const float* Vp = V + base + (size_t)k0 * HD;
        for (int t = tid; t < 64*16; t += 256) {
            const int row = t >> 4, c4 = (t & 15) * 4;
            *(float4*)&Ks[row*STRD + c4] = *(const float4*)(Kp + row*HD + c4);
            *(float4*)&Vs[row*STRD + c4] = *(const float4*)(Vp + row*HD + c4);
        }
        __syncthreads();

        // S = Q @ K^T (4x4 micro-tile)
        float s[4][4];
        #pragma unroll
        for (int i = 0; i < 4; i++)
            #pragma unroll
            for (int j = 0; j < 4; j++) s[i][j] = 0.f;
        #pragma unroll
        for (int d0 = 0; d0 < 64; d0 += 4) {
            float4 a[4], bb[4];
            #pragma unroll
            for (int i = 0; i < 4; i++) a[i]  = *(const float4*)&Qs[(r0+i)*STRD + d0];
            #pragma unroll
            for (int j = 0; j < 4; j++) bb[j] = *(const float4*)&Ks[(c0+j)*STRD + d0];
            #pragma unroll
            for (int i = 0; i < 4; i++)
                #pragma unroll
                for (int j = 0; j < 4; j++) {
                    s[i][j] = fmaf(a[i].x, bb[j].x, s[i][j]);
                    s[i][j] = fmaf(a[i].y, bb[j].y, s[i][j]);
                    s[i][j] = fmaf(a[i].z, bb[j].z, s[i][j]);
                    s[i][j] = fmaf(a[i].w, bb[j].w, s[i][j]);
                }
        }

        // masking: causal only on the diagonal tile; padding on the last valid tile
        if (k0 == q0 || (k0 + 63) >= len) {
            #pragma unroll
            for (int i = 0; i < 4; i++) {
                const int qq = q0 + r0 + i;
                #pragma unroll
                for (int j = 0; j < 4; j++) {
                    const int kk = k0 + c0 + j;
                    if (kk > qq || kk >= len) s[i][j] = -1e30f;
                }
            }
        }

        // online softmax update (row stats replicated across the 16-lane tx group)
        #pragma unroll
        for (int i = 0; i < 4; i++) {
            float tm = fmaxf(fmaxf(s[i][0], s[i][1]), fmaxf(s[i][2], s[i][3]));
            #pragma unroll
            for (int off = 1; off < 16; off <<= 1)
                tm = fmaxf(tm, __shfl_xor_sync(0xffffffffu, tm, off));
            const float mn = fmaxf(m[i], tm);
            const float alpha = __expf(m[i] - mn);
            m[i] = mn;
            float rs = 0.f;
            #pragma unroll
            for (int j = 0; j < 4; j++) { s[i][j] = __expf(s[i][j] - mn); rs += s[i][j]; }
            #pragma unroll
            for (int off = 1; off < 16; off <<= 1)
                rs += __shfl_xor_sync(0xffffffffu, rs, off);
            l[i] = l[i]*alpha + rs;
            #pragma unroll
            for (int j = 0; j < 4; j++) o[i][j] *= alpha;
        }

        __syncthreads();   // all GEMM1 reads of Ks finished
        float* Ps = Ks;    // alias
        #pragma unroll
        for (int i = 0; i < 4; i++)
            *(float4*)&Ps[(r0+i)*STRD + c0] = make_float4(s[i][0], s[i][1], s[i][2], s[i][3]);
        __syncthreads();   // Ps ready

        // O += P @ V
        #pragma unroll
        for (int kk0 = 0; kk0 < 64; kk0 += 4) {
            float4 p[4], vv[4];
            #pragma unroll
            for (int i = 0; i < 4; i++)  p[i]  = *(const float4*)&Ps[(r0+i)*STRD + kk0];
            #pragma unroll
            for (int kk = 0; kk < 4; kk++) vv[kk] = *(const float4*)&Vs[(kk0+kk)*STRD + c0];
            #pragma unroll
            for (int i = 0; i < 4; i++) {
                o[i][0] = fmaf(p[i].x, vv[0].x, fmaf(p[i].y, vv[1].x, fmaf(p[i].z, vv[2].x, fmaf(p[i].w, vv[3].x, o[i][0]))));
                o[i][1] = fmaf(p[i].x, vv[0].y, fmaf(p[i].y, vv[1].y, fmaf(p[i].z, vv[2].y, fmaf(p[i].w, vv[3].y, o[i][1]))));
                o[i][2] = fmaf(p[i].x, vv[0].z, fmaf(p[i].y, vv[1].z, fmaf(p[i].z, vv[2].z, fmaf(p[i].w, vv[3].z, o[i][2]))));
                o[i][3] = fmaf(p[i].x, vv[0].w, fmaf(p[i].y, vv[1].w, fmaf(p[i].z, vv[2].w, fmaf(p[i].w, vv[3].w, o[i][3]))));
            }
        }
    }

    // finalize + write to [B,S,D] layout
    #pragma unroll
    for (int i = 0; i < 4; i++) {
        const float inv = 1.f / l[i];
        const int qq = q0 + r0 + i;
        float4 ov = make_float4(o[i][0]*inv, o[i][1]*inv, o[i][2]*inv, o[i][3]*inv);
        *(float4*)&O[((size_t)(b*SEQ + qq))*DMODEL + h*HD + c0] = ov;
    }
}

// -------- LayerNorm over last dim (D=1024), 1 block per row --------
__global__ __launch_bounds__(256, 1) void layernorm_k(
    const float* __restrict__ x, const float* __restrict__ g,
    const float* __restrict__ be, float* __restrict__ y, int zero_pad)
{
    const int row = blockIdx.x;
    const int tid = threadIdx.x;
    const float4 v = *(const float4*)(x + (size_t)row*DMODEL + tid*4);
    float s  = v.x + v.y + v.z + v.w;
    float s2 = v.x*v.x + v.y*v.y + v.z*v.z + v.w*v.w;

    __shared__ float red[2][8];
    const int lane = tid & 31, warp = tid >> 5;
    #pragma unroll
    for (int off = 16; off > 0; off >>= 1) {
        s  += __shfl_xor_sync(0xffffffffu, s, off);
        s2 += __shfl_xor_sync(0xffffffffu, s2, off);
    }
    if (lane == 0) { red[0][warp] = s; red[1][warp] = s2; }
    __syncthreads();
    float ts = 0.f, ts2 = 0.f;
    #pragma unroll
    for (int w = 0; w < 8; w++) { ts += red[0][w]; ts2 += red[1][w]; }
    const float mu  = ts * (1.f/DMODEL);
    const float var = ts2 * (1.f/DMODEL) - mu*mu;
    const float r   = rsqrtf(var + 1e-5f);

    const int b = row >> 11, sidx = row & 2047;
    const bool zero = zero_pad && (sidx >= g_len[b]);

    const float4 gg = *(const float4*)(g  + tid*4);
    const float4 bb = *(const float4*)(be + tid*4);
    float4 o;
    o.x = zero ? 0.f : (v.x - mu)*r*gg.x + bb.x;
    o.y = zero ? 0.f : (v.y - mu)*r*gg.y + bb.y;
    o.z = zero ? 0.f : (v.z - mu)*r*gg.z + bb.z;
    o.w = zero ? 0.f : (v.w - mu)*r*gg.w + bb.w;
    *(float4*)(y + (size_t)row*DMODEL + tid*4) = o;
}

// -------- launch --------
extern "C" void kernel_launch(void* const* d_in, const int* in_sizes, int n_in,
                              void* d_out, int out_size)
{
    (void)in_sizes; (void)n_in; (void)out_size;
    const float* src = (const float*)d_in[0];
    // d_in[1] = causal_mask (deterministic triu; recomputed analytically)
    const void* pad = d_in[2];
    const float *Wq = (const float*)d_in[3],  *bq = (const float*)d_in[4];
    const float *Wk = (const float*)d_in[5],  *bk = (const float*)d_in[6];
    const float *Wv = (const float*)d_in[7],  *bv = (const float*)d_in[8];
    const float *Wo = (const float*)d_in[9],  *bo = (const float*)d_in[10];
    const float *W1 = (const float*)d_in[11], *b1 = (const float*)d_in[12];
    const float *W2 = (const float*)d_in[13], *b2 = (const float*)d_in[14];
    const float *g1 = (const float*)d_in[15], *be1 = (const float*)d_in[16];
    const float *g2 = (const float*)d_in[17], *be2 = (const float*)d_in[18];
    float* out = (float*)d_out;

    float *q, *k, *v, *attn, *x1, *src2, *ff;
    cudaGetSymbolAddress((void**)&q,    g_q);
    cudaGetSymbolAddress((void**)&k,    g_k);
    cudaGetSymbolAddress((void**)&v,    g_v);
    cudaGetSymbolAddress((void**)&attn, g_attn);
    cudaGetSymbolAddress((void**)&x1,   g_x1);
    cudaGetSymbolAddress((void**)&src2, g_src2);
    cudaGetSymbolAddress((void**)&ff,   g_ff);

    len_k<<<BATCH, 256>>>(pad);

    const dim3 gD(DMODEL/128, ROWS/128);   // (8, 32)
    sgemm_k<1><<<gD, 256>>>(src, Wq, bq, nullptr, q, ROWS, DMODEL, DMODEL);
    sgemm_k<1><<<gD, 256>>>(src, Wk, bk, nullptr, k, ROWS, DMODEL, DMODEL);
    sgemm_k<1><<<gD, 256>>>(src, Wv, bv, nullptr, v, ROWS, DMODEL, DMODEL);

    const int smem = 3 * 64 * STRD * (int)sizeof(float);   // 52224 B
    cudaFuncSetAttribute(flash_k, cudaFuncAttributeMaxDynamicSharedMemorySize, smem);
    flash_k<<<dim3(SEQ/64, NH, BATCH), 256, smem>>>(q, k, v, attn);

    sgemm_k<2><<<gD, 256>>>(attn, Wo, bo, src, x1, ROWS, DMODEL, DMODEL);
    layernorm_k<<<ROWS, 256>>>(x1, g1, be1, src2, 0);

    sgemm_k<3><<<dim3(DFF/128, ROWS/128), 256>>>(src2, W1, b1, nullptr, ff, ROWS, DFF, DMODEL);
    sgemm_k<2><<<gD, 256>>>(ff, W2, b2, src2, x1, ROWS, DMODEL, DFF);
    layernorm_k<<<ROWS, 256>>>(x1, g2, be2, out, 1);
}

// round 4
// speedup vs baseline: 2.0573x; 2.0573x over previous
#include <cuda_runtime.h>
#include <cuda_bf16.h>
#include <math.h>
#include <stdint.h>

#define BATCH 2
#define SEQ 2048
#define DMODEL 1024
#define NH 16
#define HD 64
#define DFF 4096
#define ROWS (BATCH*SEQ)   // 4096
#define STRD 68            // flash smem row stride (floats)

// ================= scratch (__device__ globals; no runtime alloc) ==========
__device__ float g_q[BATCH*NH*SEQ*HD];
__device__ float g_k[BATCH*NH*SEQ*HD];
__device__ float g_v[BATCH*NH*SEQ*HD];
__device__ float g_attn[ROWS*DMODEL];
__device__ float g_x1[ROWS*DMODEL];
__device__ float g_src2[ROWS*DMODEL];
__device__ float g_ff[(size_t)ROWS*DFF];
__device__ int   g_len[BATCH];
// transposed + hi/lo split weights, bf16 [N,K]
__device__ __nv_bfloat16 g_wqkv_hi[3072*1024];
__device__ __nv_bfloat16 g_wqkv_lo[3072*1024];
__device__ __nv_bfloat16 g_wo_hi[1024*1024];
__device__ __nv_bfloat16 g_wo_lo[1024*1024];
__device__ __nv_bfloat16 g_w1_hi[4096*1024];
__device__ __nv_bfloat16 g_w1_lo[4096*1024];
__device__ __nv_bfloat16 g_w2_hi[1024*4096];
__device__ __nv_bfloat16 g_w2_lo[1024*4096];
__device__ float g_bqkv[3072];

// ================= helpers =================================================
__device__ __forceinline__ uint32_t smem_u32(const void* p) {
    uint32_t a;
    asm("{ .reg .u64 t; cvta.to.shared.u64 t, %1; cvt.u32.u64 %0, t; }" : "=r"(a) : "l"(p));
    return a;
}
__device__ __forceinline__ void ldsm4(uint32_t a, uint32_t& r0, uint32_t& r1,
                                      uint32_t& r2, uint32_t& r3) {
    asm volatile("ldmatrix.sync.aligned.m8n8.x4.shared.b16 {%0,%1,%2,%3}, [%4];"
        : "=r"(r0), "=r"(r1), "=r"(r2), "=r"(r3) : "r"(a));
}
__device__ __forceinline__ void mma_bf16(float* d, const uint32_t* a,
                                         uint32_t b0, uint32_t b1) {
    asm volatile("mma.sync.aligned.m16n8k16.row.col.f32.bf16.bf16.f32 "
        "{%0,%1,%2,%3}, {%4,%5,%6,%7}, {%8,%9}, {%0,%1,%2,%3};"
        : "+f"(d[0]), "+f"(d[1]), "+f"(d[2]), "+f"(d[3])
        : "r"(a[0]), "r"(a[1]), "r"(a[2]), "r"(a[3]), "r"(b0), "r"(b1));
}
__device__ __forceinline__ float gelu_exact(float x) {
    return 0.5f * x * (1.0f + erff(x * 0.70710678118654752f));
}
__device__ __forceinline__ uint32_t pack_bf2(float a, float b) {
    __nv_bfloat162 t = __floats2bfloat162_rn(a, b);
    return *(uint32_t*)&t;
}

// ================= seq lengths (dtype-robust: int32 or uint8) ==============
__global__ void len_k(const void* __restrict__ mask)
{
    const int b = blockIdx.x;
    __shared__ int sbyte, smin;
    if (threadIdx.x == 0) { sbyte = 0; smin = SEQ; }
    __syncthreads();
    const unsigned* w = (const unsigned*)mask;
    for (int i = threadIdx.x; i < 1024; i += blockDim.x)
        if (w[i] > 1u) { sbyte = 1; break; }
    __syncthreads();
    int local = SEQ;
    if (sbyte) {
        const unsigned char* m = (const unsigned char*)mask + (size_t)b * SEQ;
        for (int s = threadIdx.x; s < SEQ; s += blockDim.x)
            if (m[s]) { local = s; break; }
    } else {
        const int* m = (const int*)mask + (size_t)b * SEQ;
        for (int s = threadIdx.x; s < SEQ; s += blockDim.x)
            if (m[s]) { local = s; break; }
    }
    atomicMin(&smin, local);
    __syncthreads();
    if (threadIdx.x == 0) g_len[b] = smin;
}

// ================= weight transpose + hi/lo split ==========================
// W [K,N] fp32 -> hi/lo bf16 [N,K]
__global__ void tsplit_k(const float* __restrict__ W,
                         __nv_bfloat16* __restrict__ hi,
                         __nv_bfloat16* __restrict__ lo, int K, int N)
{
    __shared__ float t[32][33];
    const int n0 = blockIdx.x * 32, k0 = blockIdx.y * 32;
    const int tx = threadIdx.x, ty = threadIdx.y;
    #pragma unroll
    for (int i = 0; i < 4; i++)
        t[ty + i*8][tx] = W[(size_t)(k0 + ty + i*8) * N + n0 + tx];
    __syncthreads();
    #pragma unroll
    for (int i = 0; i < 4; i++) {
        const float v = t[tx][ty + i*8];
        const __nv_bfloat16 h = __float2bfloat16(v);
        const __nv_bfloat16 l = __float2bfloat16(v - __bfloat162float(h));
        const size_t o = (size_t)(n0 + ty + i*8) * K + k0 + tx;
        hi[o] = h; lo[o] = l;
    }
}

__global__ void catb_k(const float* __restrict__ a, const float* __restrict__ b,
                       const float* __restrict__ c)
{
    const int i = blockIdx.x * 256 + threadIdx.x;
    if (i < 3072) g_bqkv[i] = (i < 1024) ? a[i] : (i < 2048) ? b[i-1024] : c[i-2048];
}

// ================= HMMA bf16 split GEMM ====================================
// C = A(fp32) @ B^T, B = hi+lo bf16 [N,K]; 3-term split, fp32 accum.
// Tile 128x128, K-chunk 64. 8 warps, warp tile 32(M) x 64(N).
// EPI 1: +bias, qkv scatter; 2: +bias +res; 3: +bias, exact GELU.
#define ASTR 144                      // smem row stride in bytes (64 bf16 + pad)
#define SM_AHI 0
#define SM_ALO (128*ASTR)             // 18432
#define SM_BHI (2*128*ASTR)           // 36864
#define SM_BLO (3*128*ASTR)           // 55296
#define GEMM_SMEM (4*128*ASTR)        // 73728

template<int EPI>
__global__ __launch_bounds__(256, 2) void hgemm_k(
    const float* __restrict__ A,
    const __nv_bfloat16* __restrict__ Bhi,
    const __nv_bfloat16* __restrict__ Blo,
    const float* __restrict__ bias,
    const float* __restrict__ res,
    float* __restrict__ C, float* __restrict__ C2, float* __restrict__ C3,
    int N, int K)
{
    extern __shared__ char sm[];
    const uint32_t smb = smem_u32(sm);
    const int tid = threadIdx.x;
    const int wid = tid >> 5, lane = tid & 31;
    const int wm = wid & 3, wn = wid >> 2;       // 4 warps M, 2 warps N
    const int row0 = blockIdx.y * 128;
    const int col0 = blockIdx.x * 128;

    float acc[2][8][4];
    #pragma unroll
    for (int mb = 0; mb < 2; mb++)
        #pragma unroll
        for (int nb = 0; nb < 8; nb++)
            #pragma unroll
            for (int e = 0; e < 4; e++) acc[mb][nb][e] = 0.f;

    const int nch = K >> 6;
    // ldmatrix lane addressing (row = lane%16, col-half = lane/16)
    const int lm_row  = lane & 15;
    const int lm_colb = (lane >> 4) * 16;

    for (int c = 0; c < nch; ++c) {
        __syncthreads();   // previous chunk's reads done
        // ---- A tile: 128 x 64 fp32 -> hi/lo bf16 ----
        const float* Ab = A + (size_t)row0 * K + c * 64;
        #pragma unroll
        for (int i = 0; i < 8; ++i) {
            const int f = i * 256 + tid;          // 0..2047
            const int r = f >> 4;
            const int cc = (f & 15) * 4;          // float col
            const float4 v = *(const float4*)(Ab + (size_t)r * K + cc);
            const __nv_bfloat16 h0 = __float2bfloat16(v.x), h1 = __float2bfloat16(v.y);
            const __nv_bfloat16 h2 = __float2bfloat16(v.z), h3 = __float2bfloat16(v.w);
            const uint32_t off = (uint32_t)(r * ASTR + cc * 2);
            *(uint32_t*)(sm + SM_AHI + off)     = pack_bf2(__bfloat162float(h0), __bfloat162float(h1));
            *(uint32_t*)(sm + SM_AHI + off + 4) = pack_bf2(__bfloat162float(h2), __bfloat162float(h3));
            *(uint32_t*)(sm + SM_ALO + off)     = pack_bf2(v.x - __bfloat162float(h0), v.y - __bfloat162float(h1));
            *(uint32_t*)(sm + SM_ALO + off + 4) = pack_bf2(v.z - __bfloat162float(h2), v.w - __bfloat162float(h3));
        }
        // ---- B tiles: 128 x 64 bf16 hi + lo ----
        #pragma unroll
        for (int i = 0; i < 8; ++i) {
            const int f = i * 256 + tid;          // 0..2047
            const int arr = f >> 10;              // 0 = hi, 1 = lo
            const int idx = f & 1023;
            const int r = idx >> 3;
            const int cb = (idx & 7) * 16;        // byte col
            const __nv_bfloat16* srcb = arr ? Blo : Bhi;
            const uint4 v = *(const uint4*)(srcb + (size_t)(col0 + r) * K + c * 64 + (cb >> 1));
            *(uint4*)(sm + (arr ? SM_BLO : SM_BHI) + r * ASTR + cb) = v;
        }
        __syncthreads();

        // ---- compute: 4 k16 steps ----
        #pragma unroll
        for (int st = 0; st < 4; ++st) {
            const int kb = st * 32;               // byte offset of k16 slice
            uint32_t ah[2][4], al[2][4];
            #pragma unroll
            for (int mb = 0; mb < 2; ++mb) {
                const uint32_t arow = (uint32_t)((wm*32 + mb*16 + lm_row) * ASTR + lm_colb + kb);
                ldsm4(smb + SM_AHI + arow, ah[mb][0], ah[mb][1], ah[mb][2], ah[mb][3]);
                ldsm4(smb + SM_ALO + arow, al[mb][0], al[mb][1], al[mb][2], al[mb][3]);
            }
            #pragma unroll
            for (int np = 0; np < 4; ++np) {      // pairs of n8 blocks
                const uint32_t brow = (uint32_t)((wn*64 + np*16 + lm_row) * ASTR + lm_colb + kb);
                uint32_t bh0, bh1, bh2, bh3, bl0, bl1, bl2, bl3;
                ldsm4(smb + SM_BHI + brow, bh0, bh1, bh2, bh3);
                ldsm4(smb + SM_BLO + brow, bl0, bl1, bl2, bl3);
                #pragma unroll
                for (int mb = 0; mb < 2; ++mb) {
                    // nblock np*2 (rows n0-7): frags {bh0, bh2}; np*2+1: {bh1, bh3}
                    mma_bf16(acc[mb][np*2],   ah[mb], bh0, bh2);
                    mma_bf16(acc[mb][np*2],   ah[mb], bl0, bl2);
                    mma_bf16(acc[mb][np*2],   al[mb], bh0, bh2);
                    mma_bf16(acc[mb][np*2+1], ah[mb], bh1, bh3);
                    mma_bf16(acc[mb][np*2+1], ah[mb], bl1, bl3);
                    mma_bf16(acc[mb][np*2+1], al[mb], bh1, bh3);
                }
            }
        }
    }

    // ---- epilogue ----
    const int g = lane >> 2;              // 0..7
    const int cpair = (lane & 3) * 2;
    #pragma unroll
    for (int mb = 0; mb < 2; ++mb) {
        #pragma unroll
        for (int half = 0; half < 2; ++half) {   // row g vs g+8
            const int mrow = row0 + wm*32 + mb*16 + g + half*8;
            #pragma unroll
            for (int nb = 0; nb < 8; ++nb) {
                const int n = col0 + wn*64 + nb*8 + cpair;
                float2 o;
                o.x = acc[mb][nb][half*2]   + bias[n];
                o.y = acc[mb][nb][half*2+1] + bias[n+1];
                if (EPI == 1) {
                    const int buf = n >> 10;
                    float* dst = (buf == 0) ? C : (buf == 1) ? C2 : C3;
                    const int nn = n & 1023, h = nn >> 6, d = nn & 63;
                    const int b = mrow >> 11, s = mrow & 2047;
                    *(float2*)&dst[((size_t)((b*NH + h)*SEQ + s))*HD + d] = o;
                } else if (EPI == 2) {
                    const float2 r2 = *(const float2*)&res[(size_t)mrow * N + n];
                    o.x += r2.x; o.y += r2.y;
                    *(float2*)&C[(size_t)mrow * N + n] = o;
                } else {
                    o.x = gelu_exact(o.x); o.y = gelu_exact(o.y);
                    *(float2*)&C[(size_t)mrow * N + n] = o;
                }
            }
        }
    }
}

// ================= flash attention (fp32) ==================================
__global__ __launch_bounds__(256, 1) void flash_k(
    const float* __restrict__ Q, const float* __restrict__ K,
    const float* __restrict__ V, float* __restrict__ O)
{
    extern __shared__ float smf[];
    float* Qs = smf;
    float* Ks = smf + 64*STRD;
    float* Vs = smf + 2*64*STRD;

    const int qb = blockIdx.x, h = blockIdx.y, b = blockIdx.z;
    const int q0 = qb * 64;
    const int tid = threadIdx.x;
    const int tx = tid & 15, ty = tid >> 4;
    const int r0 = ty * 4, c0 = tx * 4;

    const size_t base = ((size_t)(b*NH + h)) * SEQ * HD;
    const float* Qp = Q + base + (size_t)q0 * HD;

    for (int t = tid; t < 64*16; t += 256) {
        const int row = t >> 4, c4 = (t & 15) * 4;
        float4 v = *(const float4*)(Qp + row*HD + c4);
        v.x *= 0.125f; v.y *= 0.125f; v.z *= 0.125f; v.w *= 0.125f;
        *(float4*)&Qs[row*STRD + c4] = v;
    }

    const int len = g_len[b];
    float m[4], l[4], o[4][4];
    #pragma unroll
    for (int i = 0; i < 4; i++) {
        m[i] = -1e30f; l[i] = 0.f;
        #pragma unroll
        for (int j = 0; j < 4; j++) o[i][j] = 0.f;
    }

    const int kmax = min(q0 + 63, len - 1);
    for (int k0 = 0; k0 <= kmax; k0 += 64) {
        __syncthreads();
        const float* Kp = K + base + (size_t)k0 * HD;
        const float* Vp = V + base + (size_t)k0 * HD;
        for (int t = tid; t < 64*16; t += 256) {
            const int row = t >> 4, c4 = (t & 15) * 4;
            *(float4*)&Ks[row*STRD + c4] = *(const float4*)(Kp + row*HD + c4);
            *(float4*)&Vs[row*STRD + c4] = *(const float4*)(Vp + row*HD + c4);
        }
        __syncthreads();

        float s[4][4];
        #pragma unroll
        for (int i = 0; i < 4; i++)
            #pragma unroll
            for (int j = 0; j < 4; j++) s[i][j] = 0.f;
        #pragma unroll
        for (int d0 = 0; d0 < 64; d0 += 4) {
            float4 a[4], bb[4];
            #pragma unroll
            for (int i = 0; i < 4; i++) a[i]  = *(const float4*)&Qs[(r0+i)*STRD + d0];
            #pragma unroll
            for (int j = 0; j < 4; j++) bb[j] = *(const float4*)&Ks[(c0+j)*STRD + d0];
            #pragma unroll
            for (int i = 0; i < 4; i++)
                #pragma unroll
                for (int j = 0; j < 4; j++) {
                    s[i][j] = fmaf(a[i].x, bb[j].x, s[i][j]);
                    s[i][j] = fmaf(a[i].y, bb[j].y, s[i][j]);
                    s[i][j] = fmaf(a[i].z, bb[j].z, s[i][j]);
                    s[i][j] = fmaf(a[i].w, bb[j].w, s[i][j]);
                }
        }

        if (k0 == q0 || (k0 + 63) >= len) {
            #pragma unroll
            for (int i = 0; i < 4; i++) {
                const int qq = q0 + r0 + i;
                #pragma unroll
                for (int j = 0; j < 4; j++) {
                    const int kk = k0 + c0 + j;
                    if (kk > qq || kk >= len) s[i][j] = -1e30f;
                }
            }
        }

        #pragma unroll
        for (int i = 0; i < 4; i++) {
            float tm = fmaxf(fmaxf(s[i][0], s[i][1]), fmaxf(s[i][2], s[i][3]));
            #pragma unroll
            for (int off = 1; off < 16; off <<= 1)
                tm = fmaxf(tm, __shfl_xor_sync(0xffffffffu, tm, off));
            const float mn = fmaxf(m[i], tm);
            const float alpha = __expf(m[i] - mn);
            m[i] = mn;
            float rs = 0.f;
            #pragma unroll
            for (int j = 0; j < 4; j++) { s[i][j] = __expf(s[i][j] - mn); rs += s[i][j]; }
            #pragma unroll
            for (int off = 1; off < 16; off <<= 1)
                rs += __shfl_xor_sync(0xffffffffu, rs, off);
            l[i] = l[i]*alpha + rs;
            #pragma unroll
            for (int j = 0; j < 4; j++) o[i][j] *= alpha;
        }

        __syncthreads();
        float* Ps = Ks;
        #pragma unroll
        for (int i = 0; i < 4; i++)
            *(float4*)&Ps[(r0+i)*STRD + c0] = make_float4(s[i][0], s[i][1], s[i][2], s[i][3]);
        __syncthreads();

        #pragma unroll
        for (int kk0 = 0; kk0 < 64; kk0 += 4) {
            float4 p[4], vv[4];
            #pragma unroll
            for (int i = 0; i < 4; i++)  p[i]  = *(const float4*)&Ps[(r0+i)*STRD + kk0];
            #pragma unroll
            for (int kk = 0; kk < 4; kk++) vv[kk] = *(const float4*)&Vs[(kk0+kk)*STRD + c0];
            #pragma unroll
            for (int i = 0; i < 4; i++) {
                o[i][0] = fmaf(p[i].x, vv[0].x, fmaf(p[i].y, vv[1].x, fmaf(p[i].z, vv[2].x, fmaf(p[i].w, vv[3].x, o[i][0]))));
                o[i][1] = fmaf(p[i].x, vv[0].y, fmaf(p[i].y, vv[1].y, fmaf(p[i].z, vv[2].y, fmaf(p[i].w, vv[3].y, o[i][1]))));
                o[i][2] = fmaf(p[i].x, vv[0].z, fmaf(p[i].y, vv[1].z, fmaf(p[i].z, vv[2].z, fmaf(p[i].w, vv[3].z, o[i][2]))));
                o[i][3] = fmaf(p[i].x, vv[0].w, fmaf(p[i].y, vv[1].w, fmaf(p[i].z, vv[2].w, fmaf(p[i].w, vv[3].w, o[i][3]))));
            }
        }
    }

    #pragma unroll
    for (int i = 0; i < 4; i++) {
        const float inv = 1.f / l[i];
        const int qq = q0 + r0 + i;
        float4 ov = make_float4(o[i][0]*inv, o[i][1]*inv, o[i][2]*inv, o[i][3]*inv);
        *(float4*)&O[((size_t)(b*SEQ + qq))*DMODEL + h*HD + c0] = ov;
    }
}

// ================= LayerNorm ===============================================
__global__ __launch_bounds__(256, 1) void layernorm_k(
    const float* __restrict__ x, const float* __restrict__ g,
    const float* __restrict__ be, float* __restrict__ y, int zero_pad)
{
    const int row = blockIdx.x;
    const int tid = threadIdx.x;
    const float4 v = *(const float4*)(x + (size_t)row*DMODEL + tid*4);
    float s  = v.x + v.y + v.z + v.w;
    float s2 = v.x*v.x + v.y*v.y + v.z*v.z + v.w*v.w;

    __shared__ float red[2][8];
    const int lane = tid & 31, warp = tid >> 5;
    #pragma unroll
    for (int off = 16; off > 0; off >>= 1) {
        s  += __shfl_xor_sync(0xffffffffu, s, off);
        s2 += __shfl_xor_sync(0xffffffffu, s2, off);
    }
    if (lane == 0) { red[0][warp] = s; red[1][warp] = s2; }
    __syncthreads();
    float ts = 0.f, ts2 = 0.f;
    #pragma unroll
    for (int w = 0; w < 8; w++) { ts += red[0][w]; ts2 += red[1][w]; }
    const float mu  = ts * (1.f/DMODEL);
    const float var = ts2 * (1.f/DMODEL) - mu*mu;
    const float r   = rsqrtf(var + 1e-5f);

    const int b = row >> 11, sidx = row & 2047;
    const bool zero = zero_pad && (sidx >= g_len[b]);

    const float4 gg = *(const float4*)(g  + tid*4);
    const float4 bb = *(const float4*)(be + tid*4);
    float4 o;
    o.x = zero ? 0.f : (v.x - mu)*r*gg.x + bb.x;
    o.y = zero ? 0.f : (v.y - mu)*r*gg.y + bb.y;
    o.z = zero ? 0.f : (v.z - mu)*r*gg.z + bb.z;
    o.w = zero ? 0.f : (v.w - mu)*r*gg.w + bb.w;
    *(float4*)(y + (size_t)row*DMODEL + tid*4) = o;
}

// ================= launch ==================================================
extern "C" void kernel_launch(void* const* d_in, const int* in_sizes, int n_in,
                              void* d_out, int out_size)
{
    (void)in_sizes; (void)n_in; (void)out_size;
    const float* src = (const float*)d_in[0];
    const void* pad = d_in[2];
    const float *Wq = (const float*)d_in[3],  *bq = (const float*)d_in[4];
    const float *Wk = (const float*)d_in[5],  *bk = (const float*)d_in[6];
    const float *Wv = (const float*)d_in[7],  *bv = (const float*)d_in[8];
    const float *Wo = (const float*)d_in[9],  *bo = (const float*)d_in[10];
    const float *W1 = (const float*)d_in[11], *b1 = (const float*)d_in[12];
    const float *W2 = (const float*)d_in[13], *b2 = (const float*)d_in[14];
    const float *g1 = (const float*)d_in[15], *be1 = (const float*)d_in[16];
    const float *g2 = (const float*)d_in[17], *be2 = (const float*)d_in[18];
    float* out = (float*)d_out;

    float *q, *k, *v, *attn, *x1, *src2, *ff, *bqkv;
    __nv_bfloat16 *wqh, *wql, *woh, *wol, *w1h, *w1l, *w2h, *w2l;
    cudaGetSymbolAddress((void**)&q,    g_q);
    cudaGetSymbolAddress((void**)&k,    g_k);
    cudaGetSymbolAddress((void**)&v,    g_v);
    cudaGetSymbolAddress((void**)&attn, g_attn);
    cudaGetSymbolAddress((void**)&x1,   g_x1);
    cudaGetSymbolAddress((void**)&src2, g_src2);
    cudaGetSymbolAddress((void**)&ff,   g_ff);
    cudaGetSymbolAddress((void**)&bqkv, g_bqkv);
    cudaGetSymbolAddress((void**)&wqh,  g_wqkv_hi);
    cudaGetSymbolAddress((void**)&wql,  g_wqkv_lo);
    cudaGetSymbolAddress((void**)&woh,  g_wo_hi);
    cudaGetSymbolAddress((void**)&wol,  g_wo_lo);
    cudaGetSymbolAddress((void**)&w1h,  g_w1_hi);
    cudaGetSymbolAddress((void**)&w1l,  g_w1_lo);
    cudaGetSymbolAddress((void**)&w2h,  g_w2_hi);
    cudaGetSymbolAddress((void**)&w2l,  g_w2_lo);

    len_k<<<BATCH, 256>>>(pad);

    const dim3 tb(32, 8);
    tsplit_k<<<dim3(32, 32), tb>>>(Wq, wqh,             wql,             1024, 1024);
    tsplit_k<<<dim3(32, 32), tb>>>(Wk, wqh + 1024*1024, wql + 1024*1024, 1024, 1024);
    tsplit_k<<<dim3(32, 32), tb>>>(Wv, wqh + 2048*1024, wql + 2048*1024, 1024, 1024);
    tsplit_k<<<dim3(32, 32), tb>>>(Wo, woh, wol, 1024, 1024);
    tsplit_k<<<dim3(128, 32), tb>>>(W1, w1h, w1l, 1024, 4096);
    tsplit_k<<<dim3(32, 128), tb>>>(W2, w2h, w2l, 4096, 1024);
    catb_k<<<12, 256>>>(bq, bk, bv);

    cudaFuncSetAttribute(hgemm_k<1>, cudaFuncAttributeMaxDynamicSharedMemorySize, GEMM_SMEM);
    cudaFuncSetAttribute(hgemm_k<2>, cudaFuncAttributeMaxDynamicSharedMemorySize, GEMM_SMEM);
    cudaFuncSetAttribute(hgemm_k<3>, cudaFuncAttributeMaxDynamicSharedMemorySize, GEMM_SMEM);

    // QKV fused: [4096,1024] @ [1024,3072]
    hgemm_k<1><<<dim3(24, 32), 256, GEMM_SMEM>>>(src, wqh, wql, bqkv, nullptr,
                                                 q, k, v, 3072, 1024);

    const int fsmem = 3 * 64 * STRD * (int)sizeof(float);
    cudaFuncSetAttribute(flash_k, cudaFuncAttributeMaxDynamicSharedMemorySize, fsmem);
    flash_k<<<dim3(SEQ/64, NH, BATCH), 256, fsmem>>>(q, k, v, attn);

    hgemm_k<2><<<dim3(8, 32), 256, GEMM_SMEM>>>(attn, woh, wol, bo, src,
                                                x1, nullptr, nullptr, 1024, 1024);
    layernorm_k<<<ROWS, 256>>>(x1, g1, be1, src2, 0);

    hgemm_k<3><<<dim3(32, 32), 256, GEMM_SMEM>>>(src2, w1h, w1l, b1, nullptr,
                                                 ff, nullptr, nullptr, 4096, 1024);
    hgemm_k<2><<<dim3(8, 32), 256, GEMM_SMEM>>>(ff, w2h, w2l, b2, src2,
                                                x1, nullptr, nullptr, 1024, 4096);
    layernorm_k<<<ROWS, 256>>>(x1, g2, be2, out, 1);
}

// round 5
// speedup vs baseline: 3.0297x; 1.4727x over previous
#include <cuda_runtime.h>
#include <cuda_bf16.h>
#include <math.h>
#include <stdint.h>

#define BATCH 2
#define SEQ 2048
#define DMODEL 1024
#define NH 16
#define HD 64
#define DFF 4096
#define ROWS (BATCH*SEQ)   // 4096

// ================= scratch (__device__ globals; no runtime alloc) ==========
__device__ float g_attn[ROWS*DMODEL];
__device__ float g_x1[ROWS*DMODEL];
__device__ float g_src2[ROWS*DMODEL];
__device__ float g_ff[(size_t)ROWS*DFF];
__device__ int   g_len[BATCH];
// Q/K/V as bf16 hi/lo pairs, layout [B,H,S,hd]; Q pre-scaled by 0.125
__device__ __nv_bfloat16 g_qh[BATCH*NH*SEQ*HD];
__device__ __nv_bfloat16 g_ql[BATCH*NH*SEQ*HD];
__device__ __nv_bfloat16 g_kh[BATCH*NH*SEQ*HD];
__device__ __nv_bfloat16 g_kl[BATCH*NH*SEQ*HD];
__device__ __nv_bfloat16 g_vh[BATCH*NH*SEQ*HD];
__device__ __nv_bfloat16 g_vl[BATCH*NH*SEQ*HD];
// transposed + hi/lo split weights, bf16 [N,K]
__device__ __nv_bfloat16 g_wqkv_hi[3072*1024];
__device__ __nv_bfloat16 g_wqkv_lo[3072*1024];
__device__ __nv_bfloat16 g_wo_hi[1024*1024];
__device__ __nv_bfloat16 g_wo_lo[1024*1024];
__device__ __nv_bfloat16 g_w1_hi[4096*1024];
__device__ __nv_bfloat16 g_w1_lo[4096*1024];
__device__ __nv_bfloat16 g_w2_hi[1024*4096];
__device__ __nv_bfloat16 g_w2_lo[1024*4096];
__device__ float g_bqkv[3072];

// ================= helpers =================================================
__device__ __forceinline__ uint32_t smem_u32(const void* p) {
    uint32_t a;
    asm("{ .reg .u64 t; cvta.to.shared.u64 t, %1; cvt.u32.u64 %0, t; }" : "=r"(a) : "l"(p));
    return a;
}
__device__ __forceinline__ void ldsm4(uint32_t a, uint32_t& r0, uint32_t& r1,
                                      uint32_t& r2, uint32_t& r3) {
    asm volatile("ldmatrix.sync.aligned.m8n8.x4.shared.b16 {%0,%1,%2,%3}, [%4];"
        : "=r"(r0), "=r"(r1), "=r"(r2), "=r"(r3) : "r"(a));
}
__device__ __forceinline__ void ldsm4t(uint32_t a, uint32_t& r0, uint32_t& r1,
                                       uint32_t& r2, uint32_t& r3) {
    asm volatile("ldmatrix.sync.aligned.m8n8.x4.trans.shared.b16 {%0,%1,%2,%3}, [%4];"
        : "=r"(r0), "=r"(r1), "=r"(r2), "=r"(r3) : "r"(a));
}
__device__ __forceinline__ void mma_bf16(float* d, const uint32_t* a,
                                         uint32_t b0, uint32_t b1) {
    asm volatile("mma.sync.aligned.m16n8k16.row.col.f32.bf16.bf16.f32 "
        "{%0,%1,%2,%3}, {%4,%5,%6,%7}, {%8,%9}, {%0,%1,%2,%3};"
        : "+f"(d[0]), "+f"(d[1]), "+f"(d[2]), "+f"(d[3])
        : "r"(a[0]), "r"(a[1]), "r"(a[2]), "r"(a[3]), "r"(b0), "r"(b1));
}
__device__ __forceinline__ float gelu_exact(float x) {
    return 0.5f * x * (1.0f + erff(x * 0.70710678118654752f));
}
__device__ __forceinline__ uint32_t pack_bf2(float a, float b) {
    __nv_bfloat162 t = __floats2bfloat162_rn(a, b);
    return *(uint32_t*)&t;
}

// ================= seq lengths (dtype-robust: int32 or uint8) ==============
__global__ void len_k(const void* __restrict__ mask)
{
    const int b = blockIdx.x;
    __shared__ int sbyte, smin;
    if (threadIdx.x == 0) { sbyte = 0; smin = SEQ; }
    __syncthreads();
    const unsigned* w = (const unsigned*)mask;
    for (int i = threadIdx.x; i < 1024; i += blockDim.x)
        if (w[i] > 1u) { sbyte = 1; break; }
    __syncthreads();
    int local = SEQ;
    if (sbyte) {
        const unsigned char* m = (const unsigned char*)mask + (size_t)b * SEQ;
        for (int s = threadIdx.x; s < SEQ; s += blockDim.x)
            if (m[s]) { local = s; break; }
    } else {
        const int* m = (const int*)mask + (size_t)b * SEQ;
        for (int s = threadIdx.x; s < SEQ; s += blockDim.x)
            if (m[s]) { local = s; break; }
    }
    atomicMin(&smin, local);
    __syncthreads();
    if (threadIdx.x == 0) g_len[b] = smin;
}

// ================= weight transpose + hi/lo split ==========================
__global__ void tsplit_k(const float* __restrict__ W,
                         __nv_bfloat16* __restrict__ hi,
                         __nv_bfloat16* __restrict__ lo, int K, int N)
{
    __shared__ float t[32][33];
    const int n0 = blockIdx.x * 32, k0 = blockIdx.y * 32;
    const int tx = threadIdx.x, ty = threadIdx.y;
    #pragma unroll
    for (int i = 0; i < 4; i++)
        t[ty + i*8][tx] = W[(size_t)(k0 + ty + i*8) * N + n0 + tx];
    __syncthreads();
    #pragma unroll
    for (int i = 0; i < 4; i++) {
        const float v = t[tx][ty + i*8];
        const __nv_bfloat16 h = __float2bfloat16(v);
        const __nv_bfloat16 l = __float2bfloat16(v - __bfloat162float(h));
        const size_t o = (size_t)(n0 + ty + i*8) * K + k0 + tx;
        hi[o] = h; lo[o] = l;
    }
}

__global__ void catb_k(const float* __restrict__ a, const float* __restrict__ b,
                       const float* __restrict__ c)
{
    const int i = blockIdx.x * 256 + threadIdx.x;
    if (i < 3072) g_bqkv[i] = (i < 1024) ? a[i] : (i < 2048) ? b[i-1024] : c[i-2048];
}

// ================= HMMA bf16 split GEMM ====================================
// Tile 128x128, K-chunk 64. 8 warps, warp tile 32(M) x 64(N).
// EPI 1: +bias, scatter q/k/v as bf16 hi/lo (q scaled 0.125)
// EPI 2: +bias +res; EPI 3: +bias, exact GELU.
#define ASTR 144
#define SM_AHI 0
#define SM_ALO (128*ASTR)
#define SM_BHI (2*128*ASTR)
#define SM_BLO (3*128*ASTR)
#define GEMM_SMEM (4*128*ASTR)        // 73728

template<int EPI>
__global__ __launch_bounds__(256, 2) void hgemm_k(
    const float* __restrict__ A,
    const __nv_bfloat16* __restrict__ Bhi,
    const __nv_bfloat16* __restrict__ Blo,
    const float* __restrict__ bias,
    const float* __restrict__ res,
    float* __restrict__ C,
    __nv_bfloat16* __restrict__ qh, __nv_bfloat16* __restrict__ ql,
    __nv_bfloat16* __restrict__ kh, __nv_bfloat16* __restrict__ kl,
    __nv_bfloat16* __restrict__ vh, __nv_bfloat16* __restrict__ vl,
    int N, int K)
{
    extern __shared__ char sm[];
    const uint32_t smb = smem_u32(sm);
    const int tid = threadIdx.x;
    const int wid = tid >> 5, lane = tid & 31;
    const int wm = wid & 3, wn = wid >> 2;
    const int row0 = blockIdx.y * 128;
    const int col0 = blockIdx.x * 128;

    float acc[2][8][4];
    #pragma unroll
    for (int mb = 0; mb < 2; mb++)
        #pragma unroll
        for (int nb = 0; nb < 8; nb++)
            #pragma unroll
            for (int e = 0; e < 4; e++) acc[mb][nb][e] = 0.f;

    const int nch = K >> 6;
    const int lm_row  = lane & 15;
    const int lm_colb = (lane >> 4) * 16;

    for (int c = 0; c < nch; ++c) {
        __syncthreads();
        const float* Ab = A + (size_t)row0 * K + c * 64;
        #pragma unroll
        for (int i = 0; i < 8; ++i) {
            const int f = i * 256 + tid;
            const int r = f >> 4;
            const int cc = (f & 15) * 4;
            const float4 v = *(const float4*)(Ab + (size_t)r * K + cc);
            const __nv_bfloat16 h0 = __float2bfloat16(v.x), h1 = __float2bfloat16(v.y);
            const __nv_bfloat16 h2 = __float2bfloat16(v.z), h3 = __float2bfloat16(v.w);
            const uint32_t off = (uint32_t)(r * ASTR + cc * 2);
            *(uint32_t*)(sm + SM_AHI + off)     = pack_bf2(__bfloat162float(h0), __bfloat162float(h1));
            *(uint32_t*)(sm + SM_AHI + off + 4) = pack_bf2(__bfloat162float(h2), __bfloat162float(h3));
            *(uint32_t*)(sm + SM_ALO + off)     = pack_bf2(v.x - __bfloat162float(h0), v.y - __bfloat162float(h1));
            *(uint32_t*)(sm + SM_ALO + off + 4) = pack_bf2(v.z - __bfloat162float(h2), v.w - __bfloat162float(h3));
        }
        #pragma unroll
        for (int i = 0; i < 8; ++i) {
            const int f = i * 256 + tid;
            const int arr = f >> 10;
            const int idx = f & 1023;
            const int r = idx >> 3;
            const int cb = (idx & 7) * 16;
            const __nv_bfloat16* srcb = arr ? Blo : Bhi;
            const uint4 v = *(const uint4*)(srcb + (size_t)(col0 + r) * K + c * 64 + (cb >> 1));
            *(uint4*)(sm + (arr ? SM_BLO : SM_BHI) + r * ASTR + cb) = v;
        }
        __syncthreads();

        #pragma unroll
        for (int st = 0; st < 4; ++st) {
            const int kb = st * 32;
            uint32_t ah[2][4], al[2][4];
            #pragma unroll
            for (int mb = 0; mb < 2; ++mb) {
                const uint32_t arow = (uint32_t)((wm*32 + mb*16 + lm_row) * ASTR + lm_colb + kb);
                ldsm4(smb + SM_AHI + arow, ah[mb][0], ah[mb][1], ah[mb][2], ah[mb][3]);
                ldsm4(smb + SM_ALO + arow, al[mb][0], al[mb][1], al[mb][2], al[mb][3]);
            }
            #pragma unroll
            for (int np = 0; np < 4; ++np) {
                const uint32_t brow = (uint32_t)((wn*64 + np*16 + lm_row) * ASTR + lm_colb + kb);
                uint32_t bh0, bh1, bh2, bh3, bl0, bl1, bl2, bl3;
                ldsm4(smb + SM_BHI + brow, bh0, bh1, bh2, bh3);
                ldsm4(smb + SM_BLO + brow, bl0, bl1, bl2, bl3);
                #pragma unroll
                for (int mb = 0; mb < 2; ++mb) {
                    mma_bf16(acc[mb][np*2],   ah[mb], bh0, bh2);
                    mma_bf16(acc[mb][np*2],   ah[mb], bl0, bl2);
                    mma_bf16(acc[mb][np*2],   al[mb], bh0, bh2);
                    mma_bf16(acc[mb][np*2+1], ah[mb], bh1, bh3);
                    mma_bf16(acc[mb][np*2+1], ah[mb], bl1, bl3);
                    mma_bf16(acc[mb][np*2+1], al[mb], bh1, bh3);
                }
            }
        }
    }

    const int g = lane >> 2;
    const int cpair = (lane & 3) * 2;
    #pragma unroll
    for (int mb = 0; mb < 2; ++mb) {
        #pragma unroll
        for (int half = 0; half < 2; ++half) {
            const int mrow = row0 + wm*32 + mb*16 + g + half*8;
            #pragma unroll
            for (int nb = 0; nb < 8; ++nb) {
                const int n = col0 + wn*64 + nb*8 + cpair;
                float2 o;
                o.x = acc[mb][nb][half*2]   + bias[n];
                o.y = acc[mb][nb][half*2+1] + bias[n+1];
                if (EPI == 1) {
                    const int buf = n >> 10;
                    if (buf == 0) { o.x *= 0.125f; o.y *= 0.125f; }
                    __nv_bfloat16* dh = (buf == 0) ? qh : (buf == 1) ? kh : vh;
                    __nv_bfloat16* dl = (buf == 0) ? ql : (buf == 1) ? kl : vl;
                    const int nn = n & 1023, h = nn >> 6, d = nn & 63;
                    const int b = mrow >> 11, s = mrow & 2047;
                    const size_t off = ((size_t)((b*NH + h)*SEQ + s))*HD + d;
                    const uint32_t hv = pack_bf2(o.x, o.y);
                    __nv_bfloat162 hv2 = *(__nv_bfloat162*)&hv;
                    const uint32_t lv = pack_bf2(o.x - __bfloat162float(hv2.x),
                                                 o.y - __bfloat162float(hv2.y));
                    *(uint32_t*)&dh[off] = hv;
                    *(uint32_t*)&dl[off] = lv;
                } else if (EPI == 2) {
                    const float2 r2 = *(const float2*)&res[(size_t)mrow * N + n];
                    o.x += r2.x; o.y += r2.y;
                    *(float2*)&C[(size_t)mrow * N + n] = o;
                } else {
                    o.x = gelu_exact(o.x); o.y = gelu_exact(o.y);
                    *(float2*)&C[(size_t)mrow * N + n] = o;
                }
            }
        }
    }
}

// ================= flash attention, HMMA bf16 split ========================
// 128 q-rows per block, 8 warps (warp w owns rows w*16..+16), kv tiles of 64.
// smem: Khi @0, Klo @9216, Vhi @18432, Vlo @27648 (rows 64, stride 144B)
#define FLASH_SMEM 36864

__global__ __launch_bounds__(256) void flashb_k(
    const __nv_bfloat16* __restrict__ Qh, const __nv_bfloat16* __restrict__ Ql,
    const __nv_bfloat16* __restrict__ Kh, const __nv_bfloat16* __restrict__ Kl,
    const __nv_bfloat16* __restrict__ Vh, const __nv_bfloat16* __restrict__ Vl,
    float* __restrict__ O)
{
    extern __shared__ char sm[];
    const uint32_t smb = smem_u32(sm);
    const int qb = blockIdx.x, h = blockIdx.y, b = blockIdx.z;
    const int q0 = qb * 128;
    const int tid = threadIdx.x;
    const int wid = tid >> 5, lane = tid & 31;
    const int len = g_len[b];

    // Skipped padded q-tiles: zero output (rows are zeroed by the final LN anyway)
    if (q0 >= len) {
        const float4 z = make_float4(0.f, 0.f, 0.f, 0.f);
        for (int i = tid; i < 128*16; i += 256) {
            const int r = i >> 4, c4 = (i & 15) * 4;
            *(float4*)&O[((size_t)(b*SEQ + q0 + r))*DMODEL + h*HD + c4] = z;
        }
        return;
    }

    const size_t base = ((size_t)(b*NH + h)) * SEQ * HD;
    const int qrow = q0 + wid*16 + (lane >> 2);

    // Q fragments direct from gmem: [kstep][reg]
    uint32_t qhf[4][4], qlf[4][4];
    #pragma unroll
    for (int st = 0; st < 4; ++st)
        #pragma unroll
        for (int rg = 0; rg < 4; ++rg) {
            const int rr = qrow + (rg & 1) * 8;
            const int kk = st*16 + (rg >> 1)*8 + (lane & 3)*2;
            qhf[st][rg] = *(const uint32_t*)&Qh[base + (size_t)rr*HD + kk];
            qlf[st][rg] = *(const uint32_t*)&Ql[base + (size_t)rr*HD + kk];
        }

    float m[2] = {-1e30f, -1e30f}, l[2] = {0.f, 0.f};
    float o[8][4];
    #pragma unroll
    for (int nb = 0; nb < 8; nb++)
        #pragma unroll
        for (int e = 0; e < 4; e++) o[nb][e] = 0.f;

    const int kmax = min(q0 + 127, len - 1);
    for (int k0 = 0; k0 <= kmax; k0 += 64) {
        __syncthreads();
        // load K/V hi/lo tiles (64 x 64 bf16 each)
        for (int i = tid; i < 2048; i += 256) {
            const int arr = i >> 9;           // 0:Kh 1:Kl 2:Vh 3:Vl
            const int idx = i & 511;
            const int r = idx >> 3;
            const int cb = (idx & 7) * 16;    // bytes
            const __nv_bfloat16* src = (arr == 0) ? Kh : (arr == 1) ? Kl :
                                       (arr == 2) ? Vh : Vl;
            const uint4 val = *(const uint4*)&src[base + (size_t)(k0 + r)*HD + (cb >> 1)];
            *(uint4*)(sm + arr*9216 + r*144 + cb) = val;
        }
        __syncthreads();

        // ---- S = Q K^T (3-term split) ----
        float s[8][4];
        #pragma unroll
        for (int nb = 0; nb < 8; nb++)
            #pragma unroll
            for (int e = 0; e < 4; e++) s[nb][e] = 0.f;
        #pragma unroll
        for (int np = 0; np < 4; ++np) {
            #pragma unroll
            for (int st = 0; st < 4; ++st) {
                const uint32_t a = smb + (uint32_t)((np*16 + (lane & 15))*144 + ((lane >> 4)*16) + st*32);
                uint32_t kh0, kh1, kh2, kh3, kl0, kl1, kl2, kl3;
                ldsm4(a,        kh0, kh1, kh2, kh3);
                ldsm4(a + 9216, kl0, kl1, kl2, kl3);
                mma_bf16(s[np*2],   qhf[st], kh0, kh2);
                mma_bf16(s[np*2],   qhf[st], kl0, kl2);
                mma_bf16(s[np*2],   qlf[st], kh0, kh2);
                mma_bf16(s[np*2+1], qhf[st], kh1, kh3);
                mma_bf16(s[np*2+1], qhf[st], kl1, kl3);
                mma_bf16(s[np*2+1], qlf[st], kh1, kh3);
            }
        }

        // ---- masking (boundary tiles only) ----
        if (k0 + 63 >= q0 || k0 + 63 >= len) {
            #pragma unroll
            for (int nb = 0; nb < 8; ++nb)
                #pragma unroll
                for (int e = 0; e < 4; ++e) {
                    const int qq = qrow + (e >> 1) * 8;
                    const int kk = k0 + nb*8 + (lane & 3)*2 + (e & 1);
                    if (kk > qq || kk >= len) s[nb][e] = -1e30f;
                }
        }

        // ---- online softmax (rows: half 0 = qrow, half 1 = qrow+8) ----
        #pragma unroll
        for (int hh = 0; hh < 2; ++hh) {
            float tm = -1e30f;
            #pragma unroll
            for (int nb = 0; nb < 8; ++nb)
                tm = fmaxf(tm, fmaxf(s[nb][hh*2], s[nb][hh*2+1]));
            tm = fmaxf(tm, __shfl_xor_sync(0xffffffffu, tm, 1));
            tm = fmaxf(tm, __shfl_xor_sync(0xffffffffu, tm, 2));
            const float mn = fmaxf(m[hh], tm);
            const float alpha = __expf(m[hh] - mn);
            m[hh] = mn;
            float rs = 0.f;
            #pragma unroll
            for (int nb = 0; nb < 8; ++nb) {
                s[nb][hh*2]   = __expf(s[nb][hh*2]   - mn);
                s[nb][hh*2+1] = __expf(s[nb][hh*2+1] - mn);
                rs += s[nb][hh*2] + s[nb][hh*2+1];
            }
            rs += __shfl_xor_sync(0xffffffffu, rs, 1);
            rs += __shfl_xor_sync(0xffffffffu, rs, 2);
            l[hh] = l[hh]*alpha + rs;
            #pragma unroll
            for (int nb = 0; nb < 8; ++nb) {
                o[nb][hh*2] *= alpha; o[nb][hh*2+1] *= alpha;
            }
        }

        // ---- O += P V (3-term split; P repacked from s fragments) ----
        #pragma unroll
        for (int st = 0; st < 4; ++st) {
            uint32_t ph[4], pl[4];
            #pragma unroll
            for (int j = 0; j < 2; ++j) {       // s blocks 2st+j
                const float e0 = s[2*st+j][0], e1 = s[2*st+j][1];
                const float e2 = s[2*st+j][2], e3 = s[2*st+j][3];
                const uint32_t hv01 = pack_bf2(e0, e1);
                const uint32_t hv23 = pack_bf2(e2, e3);
                const __nv_bfloat162 h01 = *(const __nv_bfloat162*)&hv01;
                const __nv_bfloat162 h23 = *(const __nv_bfloat162*)&hv23;
                ph[j*0 + (j ? 2 : 0)]     = hv01;   // a0 / a2
                ph[(j ? 3 : 1)]           = hv23;   // a1 / a3
                pl[(j ? 2 : 0)] = pack_bf2(e0 - __bfloat162float(h01.x),
                                           e1 - __bfloat162float(h01.y));
                pl[(j ? 3 : 1)] = pack_bf2(e2 - __bfloat162float(h23.x),
                                           e3 - __bfloat162float(h23.y));
            }
            #pragma unroll
            for (int np = 0; np < 4; ++np) {
                const uint32_t a = smb + 18432u +
                    (uint32_t)((st*16 + (lane & 15))*144 + (np*16 + (lane >> 4)*8)*2);
                uint32_t vh0, vh1, vh2, vh3, vl0, vl1, vl2, vl3;
                ldsm4t(a,        vh0, vh1, vh2, vh3);
                ldsm4t(a + 9216, vl0, vl1, vl2, vl3);
                mma_bf16(o[np*2],   ph, vh0, vh1);
                mma_bf16(o[np*2],   pl, vh0, vh1);
                mma_bf16(o[np*2],   ph, vl0, vl1);
                mma_bf16(o[np*2+1], ph, vh2, vh3);
                mma_bf16(o[np*2+1], pl, vh2, vh3);
                mma_bf16(o[np*2+1], ph, vl2, vl3);
            }
        }
    }

    // ---- finalize + write [B,S,D] ----
    #pragma unroll
    for (int hh = 0; hh < 2; ++hh) {
        const float inv = 1.f / l[hh];
        const int qq = qrow + hh*8;
        #pragma unroll
        for (int nb = 0; nb < 8; ++nb) {
            float2 ov;
            ov.x = o[nb][hh*2]   * inv;
            ov.y = o[nb][hh*2+1] * inv;
            *(float2*)&O[((size_t)(b*SEQ + qq))*DMODEL + h*HD + nb*8 + (lane & 3)*2] = ov;
        }
    }
}

// ================= LayerNorm ===============================================
__global__ __launch_bounds__(256, 1) void layernorm_k(
    const float* __restrict__ x, const float* __restrict__ g,
    const float* __restrict__ be, float* __restrict__ y, int zero_pad)
{
    const int row = blockIdx.x;
    const int tid = threadIdx.x;
    const float4 v = *(const float4*)(x + (size_t)row*DMODEL + tid*4);
    float s  = v.x + v.y + v.z + v.w;
    float s2 = v.x*v.x + v.y*v.y + v.z*v.z + v.w*v.w;

    __shared__ float red[2][8];
    const int lane = tid & 31, warp = tid >> 5;
    #pragma unroll
    for (int off = 16; off > 0; off >>= 1) {
        s  += __shfl_xor_sync(0xffffffffu, s, off);
        s2 += __shfl_xor_sync(0xffffffffu, s2, off);
    }
    if (lane == 0) { red[0][warp] = s; red[1][warp] = s2; }
    __syncthreads();
    float ts = 0.f, ts2 = 0.f;
    #pragma unroll
    for (int w = 0; w < 8; w++) { ts += red[0][w]; ts2 += red[1][w]; }
    const float mu  = ts * (1.f/DMODEL);
    const float var = ts2 * (1.f/DMODEL) - mu*mu;
    const float r   = rsqrtf(var + 1e-5f);

    const int b = row >> 11, sidx = row & 2047;
    const bool zero = zero_pad && (sidx >= g_len[b]);

    const float4 gg = *(const float4*)(g  + tid*4);
    const float4 bb = *(const float4*)(be + tid*4);
    float4 o;
    o.x = zero ? 0.f : (v.x - mu)*r*gg.x + bb.x;
    o.y = zero ? 0.f : (v.y - mu)*r*gg.y + bb.y;
    o.z = zero ? 0.f : (v.z - mu)*r*gg.z + bb.z;
    o.w = zero ? 0.f : (v.w - mu)*r*gg.w + bb.w;
    *(float4*)(y + (size_t)row*DMODEL + tid*4) = o;
}

// ================= launch ==================================================
extern "C" void kernel_launch(void* const* d_in, const int* in_sizes, int n_in,
                              void* d_out, int out_size)
{
    (void)in_sizes; (void)n_in; (void)out_size;
    const float* src = (const float*)d_in[0];
    const void* pad = d_in[2];
    const float *Wq = (const float*)d_in[3],  *bq = (const float*)d_in[4];
    const float *Wk = (const float*)d_in[5],  *bk = (const float*)d_in[6];
    const float *Wv = (const float*)d_in[7],  *bv = (const float*)d_in[8];
    const float *Wo = (const float*)d_in[9],  *bo = (const float*)d_in[10];
    const float *W1 = (const float*)d_in[11], *b1 = (const float*)d_in[12];
    const float *W2 = (const float*)d_in[13], *b2 = (const float*)d_in[14];
    const float *g1 = (const float*)d_in[15], *be1 = (const float*)d_in[16];
    const float *g2 = (const float*)d_in[17], *be2 = (const float*)d_in[18];
    float* out = (float*)d_out;

    float *attn, *x1, *src2, *ff, *bqkv;
    __nv_bfloat16 *qh, *ql, *kh, *kl, *vh, *vl;
    __nv_bfloat16 *wqh, *wql, *woh, *wol, *w1h, *w1l, *w2h, *w2l;
    cudaGetSymbolAddress((void**)&attn, g_attn);
    cudaGetSymbolAddress((void**)&x1,   g_x1);
    cudaGetSymbolAddress((void**)&src2, g_src2);
    cudaGetSymbolAddress((void**)&ff,   g_ff);
    cudaGetSymbolAddress((void**)&bqkv, g_bqkv);
    cudaGetSymbolAddress((void**)&qh,   g_qh);
    cudaGetSymbolAddress((void**)&ql,   g_ql);
    cudaGetSymbolAddress((void**)&kh,   g_kh);
    cudaGetSymbolAddress((void**)&kl,   g_kl);
    cudaGetSymbolAddress((void**)&vh,   g_vh);
    cudaGetSymbolAddress((void**)&vl,   g_vl);
    cudaGetSymbolAddress((void**)&wqh,  g_wqkv_hi);
    cudaGetSymbolAddress((void**)&wql,  g_wqkv_lo);
    cudaGetSymbolAddress((void**)&woh,  g_wo_hi);
    cudaGetSymbolAddress((void**)&wol,  g_wo_lo);
    cudaGetSymbolAddress((void**)&w1h,  g_w1_hi);
    cudaGetSymbolAddress((void**)&w1l,  g_w1_lo);
    cudaGetSymbolAddress((void**)&w2h,  g_w2_hi);
    cudaGetSymbolAddress((void**)&w2l,  g_w2_lo);

    len_k<<<BATCH, 256>>>(pad);

    const dim3 tb(32, 8);
    tsplit_k<<<dim3(32, 32), tb>>>(Wq, wqh,             wql,             1024, 1024);
    tsplit_k<<<dim3(32, 32), tb>>>(Wk, wqh + 1024*1024, wql + 1024*1024, 1024, 1024);
    tsplit_k<<<dim3(32, 32), tb>>>(Wv, wqh + 2048*1024, wql + 2048*1024, 1024, 1024);
    tsplit_k<<<dim3(32, 32), tb>>>(Wo, woh, wol, 1024, 1024);
    tsplit_k<<<dim3(128, 32), tb>>>(W1, w1h, w1l, 1024, 4096);
    tsplit_k<<<dim3(32, 128), tb>>>(W2, w2h, w2l, 4096, 1024);
    catb_k<<<12, 256>>>(bq, bk, bv);

    cudaFuncSetAttribute(hgemm_k<1>, cudaFuncAttributeMaxDynamicSharedMemorySize, GEMM_SMEM);
    cudaFuncSetAttribute(hgemm_k<2>, cudaFuncAttributeMaxDynamicSharedMemorySize, GEMM_SMEM);
    cudaFuncSetAttribute(hgemm_k<3>, cudaFuncAttributeMaxDynamicSharedMemorySize, GEMM_SMEM);

    // QKV fused: [4096,1024] @ [1024,3072] -> bf16 hi/lo q,k,v
    hgemm_k<1><<<dim3(24, 32), 256, GEMM_SMEM>>>(src, wqh, wql, bqkv, nullptr,
                                                 nullptr, qh, ql, kh, kl, vh, vl,
                                                 3072, 1024);

    cudaFuncSetAttribute(flashb_k, cudaFuncAttributeMaxDynamicSharedMemorySize, FLASH_SMEM);
    flashb_k<<<dim3(SEQ/128, NH, BATCH), 256, FLASH_SMEM>>>(qh, ql, kh, kl, vh, vl, attn);

    hgemm_k<2><<<dim3(8, 32), 256, GEMM_SMEM>>>(attn, woh, wol, bo, src, x1,
                                                nullptr, nullptr, nullptr, nullptr,
                                                nullptr, nullptr, 1024, 1024);
    layernorm_k<<<ROWS, 256>>>(x1, g1, be1, src2, 0);

    hgemm_k<3><<<dim3(32, 32), 256, GEMM_SMEM>>>(src2, w1h, w1l, b1, nullptr, ff,
                                                 nullptr, nullptr, nullptr, nullptr,
                                                 nullptr, nullptr, 4096, 1024);
    hgemm_k<2><<<dim3(8, 32), 256, GEMM_SMEM>>>(ff, w2h, w2l, b2, src2, x1,
                                                nullptr, nullptr, nullptr, nullptr,
                                                nullptr, nullptr, 1024, 4096);
    layernorm_k<<<ROWS, 256>>>(x1, g2, be2, out, 1);
}